// round 2
// baseline (speedup 1.0000x reference)
#include <cuda_runtime.h>
#include <cstddef>

// BinaryMaskEdgeSmoothing — exact integer-combinatorics reduction (validated R1,
// rel_err=0.0):
//   S9 = 3x3 sum, edges = 9*c - S9, n = Gauss numerator = S9 + m3 + vcen
//   out = (n + (|edges| < 5.5 ? c : 0)) > 8.5
// R2 changes: RPT 16->32 (halo amp 1.125->1.0625), warp-shuffle horizontal
// halos (kill 2 scalar LDG/row/thread), streaming stores.

#define Wd 1024
#define Hd 1024
#define RPT 32   // output rows per thread

__device__ __forceinline__ void load_row6(const float* __restrict__ base, int r,
                                          int j, int lane, float v[6]) {
    if ((unsigned)r >= (unsigned)Hd) {            // uniform per warp (zero pad)
        v[0] = v[1] = v[2] = v[3] = v[4] = v[5] = 0.f;
        return;
    }
    const float* p = base + (size_t)r * Wd + (j << 2);
    float4 cc = __ldg((const float4*)p);
    // horizontal halos from neighbor lanes; only lanes 0/31 touch memory
    float left  = __shfl_up_sync(0xffffffffu,  cc.w, 1);
    float right = __shfl_down_sync(0xffffffffu, cc.x, 1);
    if (lane == 0)  left  = (j > 0)            ? __ldg(p - 1) : 0.f;
    if (lane == 31) right = (j < (Wd / 4 - 1)) ? __ldg(p + 4) : 0.f;
    v[0] = left; v[1] = cc.x; v[2] = cc.y; v[3] = cc.z; v[4] = cc.w; v[5] = right;
}

__global__ void __launch_bounds__(256)
mask_smooth_kernel(const float* __restrict__ in, float* __restrict__ out) {
    const int img  = blockIdx.y;
    const int r0   = blockIdx.x * RPT;
    const int j    = threadIdx.x;                 // float4 column index 0..255
    const int lane = threadIdx.x & 31;

    const float* base = in  + (size_t)img * Hd * Wd;
    float*       ob   = out + (size_t)img * Hd * Wd;

    float a[6], b[6], c[6];                       // rows r-1, r, r+1 (6-col window)
    load_row6(base, r0 - 1, j, lane, a);
    load_row6(base, r0,     j, lane, b);

    #pragma unroll 8
    for (int rr = 0; rr < RPT; ++rr) {
        const int r = r0 + rr;
        load_row6(base, r + 1, j, lane, c);

        float cs[6];                              // vertical column sums
        #pragma unroll
        for (int k = 0; k < 6; ++k) cs[k] = a[k] + b[k] + c[k];

        float res[4];
        #pragma unroll
        for (int i = 0; i < 4; ++i) {
            float S9    = cs[i] + cs[i + 1] + cs[i + 2];
            float m3    = b[i]  + b[i + 1]  + b[i + 2];
            float cv    = b[i + 1];
            float vcen  = cs[i + 1] + cv;         // t_c + 2*m_c + b_c
            float n     = S9 + m3 + vcen;         // Gauss numerator, 0..16
            float edges = fmaf(9.f, cv, -S9);     // Laplacian response, -9..9
            float bonus = (fabsf(edges) < 5.5f) ? cv : 0.f;
            res[i] = (n + bonus > 8.5f) ? 1.f : 0.f;
        }

        float4 o;
        o.x = res[0]; o.y = res[1]; o.z = res[2]; o.w = res[3];
        __stcs((float4*)(ob + (size_t)r * Wd + (j << 2)), o);   // streaming store

        #pragma unroll
        for (int k = 0; k < 6; ++k) { a[k] = b[k]; b[k] = c[k]; }
    }
}

extern "C" void kernel_launch(void* const* d_in, const int* in_sizes, int n_in,
                              void* d_out, int out_size) {
    const float* mask = (const float*)d_in[0];    // [B*C, H, W] fp32 binary
    float*       outp = (float*)d_out;
    const int nimg = in_sizes[0] / (Hd * Wd);     // 64 for the reference shapes

    dim3 grid(Hd / RPT, nimg);
    mask_smooth_kernel<<<grid, 256>>>(mask, outp);
}

// round 6
// speedup vs baseline: 1.2790x; 1.2790x over previous
#include <cuda_runtime.h>
#include <cstddef>

// BinaryMaskEdgeSmoothing — exact integer-combinatorics reduction (validated
// R1, rel_err=0.0):
//   S9 = 3x3 sum, edges = 9*c - S9, n = Gauss numerator = S9 + m3 + vcen
//   out = (n + (|edges| < 5.5 ? c : 0)) > 8.5
// R6 == R3/R4/R5 resubmission (none ran: broker GPUAcquisitionTimeout).
// Structure: R1 (RPT=16, scalar halos, grid 4096) + one-iteration row
// prefetch + streaming stores.

#define Wd 1024
#define Hd 1024
#define RPT 16   // output rows per thread

__device__ __forceinline__ void load_row(const float* __restrict__ base, int r,
                                         int j, float v[6]) {
    if ((unsigned)r >= (unsigned)Hd) {            // SAME zero padding
        v[0] = v[1] = v[2] = v[3] = v[4] = v[5] = 0.f;
        return;
    }
    const float* p = base + (size_t)r * Wd + (j << 2);
    float4 cc = __ldg((const float4*)p);
    v[0] = (j > 0) ? __ldg(p - 1) : 0.f;          // left halo (L1-hit)
    v[1] = cc.x; v[2] = cc.y; v[3] = cc.z; v[4] = cc.w;
    v[5] = (j < (Wd / 4 - 1)) ? __ldg(p + 4) : 0.f;  // right halo (L1-hit)
}

__global__ void __launch_bounds__(256)
mask_smooth_kernel(const float* __restrict__ in, float* __restrict__ out) {
    const int img = blockIdx.y;
    const int r0  = blockIdx.x * RPT;
    const int j   = threadIdx.x;                  // float4 column index 0..255

    const float* base = in  + (size_t)img * Hd * Wd;
    float*       ob   = out + (size_t)img * Hd * Wd;

    float a[6], b[6], c[6], n6[6];                // rows r-1, r, r+1, prefetch r+2
    load_row(base, r0 - 1, j, a);
    load_row(base, r0,     j, b);
    load_row(base, r0 + 1, j, c);

    #pragma unroll
    for (int rr = 0; rr < RPT; ++rr) {
        const int r = r0 + rr;

        // Prefetch next iteration's bottom row FIRST — its latency overlaps
        // this iteration's arithmetic + store.
        load_row(base, r + 2, j, n6);

        float cs[6];                              // vertical column sums
        #pragma unroll
        for (int k = 0; k < 6; ++k) cs[k] = a[k] + b[k] + c[k];

        float res[4];
        #pragma unroll
        for (int i = 0; i < 4; ++i) {
            float S9    = cs[i] + cs[i + 1] + cs[i + 2];
            float m3    = b[i]  + b[i + 1]  + b[i + 2];
            float cv    = b[i + 1];
            float vcen  = cs[i + 1] + cv;         // t_c + 2*m_c + b_c
            float nG    = S9 + m3 + vcen;         // Gauss numerator, 0..16
            float edges = fmaf(9.f, cv, -S9);     // Laplacian response, -9..9
            float bonus = (fabsf(edges) < 5.5f) ? cv : 0.f;
            res[i] = (nG + bonus > 8.5f) ? 1.f : 0.f;
        }

        float4 o;
        o.x = res[0]; o.y = res[1]; o.z = res[2]; o.w = res[3];
        __stcs((float4*)(ob + (size_t)r * Wd + (j << 2)), o);   // streaming store

        #pragma unroll
        for (int k = 0; k < 6; ++k) { a[k] = b[k]; b[k] = c[k]; c[k] = n6[k]; }
    }
}

extern "C" void kernel_launch(void* const* d_in, const int* in_sizes, int n_in,
                              void* d_out, int out_size) {
    const float* mask = (const float*)d_in[0];    // [B*C, H, W] fp32 binary
    float*       outp = (float*)d_out;
    const int nimg = in_sizes[0] / (Hd * Wd);     // 64 for the reference shapes

    dim3 grid(Hd / RPT, nimg);
    mask_smooth_kernel<<<grid, 256>>>(mask, outp);
}